// round 14
// baseline (speedup 1.0000x reference)
#include <cuda_runtime.h>
#include <cuda_bf16.h>
#include <cstdint>

#define NS 32
#define NV 8
#define N_NODES 16384
#define N_EDGES 131072
#define NEF 128
#define HID 128
#define WN 1600
#define WNP 1664            /* padded to 13*128 */
#define DD 56
#define INV_SQRT3 0.57735026918962576451f
#define PATH_NORM 0.15811388300841897f /* 1/sqrt(40) */
#define EPS 1e-5f

// ---------------- scratch (static device globals) ----------------
__device__ __nv_bfloat16 g_h_hi[(size_t)N_EDGES * HID];   // 32 MB
__device__ __nv_bfloat16 g_h_lo[(size_t)N_EDGES * HID];   // 32 MB
__device__ __nv_bfloat16 g_W2t_hi[(size_t)WNP * HID];     // [c][k]
__device__ __nv_bfloat16 g_W2t_lo[(size_t)WNP * HID];
__device__ float g_sums[(size_t)N_NODES * DD];
__device__ float g_cnt[N_NODES];
__device__ float g_pre[(size_t)N_NODES * DD];
__device__ float g_stats[72];
__device__ int   g_idx32;

// ---------------- f32x2 helpers (K1 SGEMM) ----------------
#define PACKDUP(dst, s) do { unsigned _u = __float_as_uint(s); \
    asm("mov.b64 %0, {%1, %1};" : "=l"(dst) : "r"(_u)); } while (0)
#define FMA2(d, a, b) asm("fma.rn.f32x2 %0, %1, %2, %0;" : "+l"(d) : "l"(a), "l"(b))
#define UNPACK2(lo, hi, v) do { unsigned _lo, _hi; \
    asm("mov.b64 {%0, %1}, %2;" : "=r"(_lo), "=r"(_hi) : "l"(v)); \
    lo = __uint_as_float(_lo); hi = __uint_as_float(_hi); } while (0)

typedef unsigned long long u64;

__device__ __forceinline__ uint32_t smem_u32(const void* p) {
    uint32_t a;
    asm("{ .reg .u64 t; cvta.to.shared.u64 t, %1; cvt.u32.u64 %0, t; }" : "=r"(a) : "l"(p));
    return a;
}

#define LDSM_X4(r0, r1, r2, r3, addr) \
    asm volatile("ldmatrix.sync.aligned.m8n8.x4.shared.b16 {%0,%1,%2,%3}, [%4];" \
        : "=r"(r0), "=r"(r1), "=r"(r2), "=r"(r3) : "r"(addr))

#define MMA_BF16(c, a0, a1, a2, a3, b0, b1) \
    asm volatile("mma.sync.aligned.m16n8k16.row.col.f32.bf16.bf16.f32 " \
        "{%0,%1,%2,%3}, {%4,%5,%6,%7}, {%8,%9}, {%0,%1,%2,%3};" \
        : "+f"((c)[0]), "+f"((c)[1]), "+f"((c)[2]), "+f"((c)[3]) \
        : "r"(a0), "r"(a1), "r"(a2), "r"(a3), "r"(b0), "r"(b1))

// ---------------- K2 SMEM layout (byte offsets) ----------------
// A/B tiles: 128 rows x 136 bf16 (stride 272 B, 16B-aligned)
#define TSTRIDE 272
#define TILE_B  34816           /* 128*272 */
#define SA_HI 0
#define SA_LO 34816
#define SB_HI 69632
#define SB_LO 104448
#define SCS   69632             /* Cs aliases B region; 128x129 floats = 66048 B */
#define CS_STRIDE 129
#define SB2S  139264
#define SSXS  139776
#define SXSH  156160
#define SDVV  172544
#define SXVS  176640
#define SSVS  188928
#define SESRC 190464
#define K2_SMEM 190976

#define K2_THREADS 512

// ============================================================
// K0: zero accumulators + detect edge_index dtype
// ============================================================
__global__ void k0_zero(const long long* __restrict__ eidx) {
    int idx = blockIdx.x * 256 + threadIdx.x;
    if (idx < N_NODES * DD) g_sums[idx] = 0.f;
    if (idx < N_NODES)      g_cnt[idx]  = 0.f;
    if (idx < 72)           g_stats[idx] = 0.f;
    if (blockIdx.x == 0 && threadIdx.x == 0) {
        int is32 = 0;
        for (int i = 0; i < 64; ++i) {
            long long v = eidx[i];
            if (v < 0 || v >= N_NODES) { is32 = 1; break; }
        }
        g_idx32 = is32;
    }
}

// ============================================================
// K_prep: W2^T -> bf16 hi/lo planes  g_W2t[c][k], zero-padded c>=1600
// ============================================================
__global__ void k_prep(const float* __restrict__ W2) {
    int idx = blockIdx.x * 256 + threadIdx.x;   // WNP*HID total
    if (idx >= WNP * HID) return;
    int c = idx >> 7, k = idx & 127;
    float w = (c < WN) ? W2[(size_t)k * WN + c] : 0.f;
    __nv_bfloat16 hi = __float2bfloat16(w);
    float r = w - __bfloat162float(hi);
    g_W2t_hi[idx] = hi;
    g_W2t_lo[idx] = __float2bfloat16(r);
}

// ============================================================
// K1: h = relu(edge_attr @ W1 + b1) -> bf16 hi/lo planes
// ============================================================
__global__ __launch_bounds__(256, 1)
void k1_gemm_relu(const float* __restrict__ ea, const float* __restrict__ W1,
                  const float* __restrict__ b1) {
    extern __shared__ float sm[];
    float* As = sm;          // 128x128
    float* Bs = sm + 16384;  // 128x128
    int tid = threadIdx.x;
    int e0 = blockIdx.x * 128;

    for (int it = 0; it < 16; ++it) {
        int idx = tid + it * 256;
        int r = idx >> 5, c4 = idx & 31;
        *(float4*)&As[r * 128 + c4 * 4] = *(const float4*)&ea[(size_t)(e0 + r) * NEF + c4 * 4];
        *(float4*)&Bs[r * 128 + c4 * 4] = *(const float4*)&W1[(size_t)r * HID + c4 * 4];
    }
    __syncthreads();

    int tx = tid & 15, ty = tid >> 4;
    u64 acc[8][4];
    #pragma unroll
    for (int i = 0; i < 8; ++i)
        #pragma unroll
        for (int j = 0; j < 4; ++j) acc[i][j] = 0ull;

    #pragma unroll 2
    for (int k4 = 0; k4 < 32; ++k4) {
        int k0 = k4 * 4;
        float4 av[8];
        #pragma unroll
        for (int mi = 0; mi < 8; ++mi) {
            int m = (mi < 4) ? (ty * 4 + mi) : (64 + ty * 4 + mi - 4);
            av[mi] = *(const float4*)&As[m * 128 + k0];
        }
        #pragma unroll
        for (int kk = 0; kk < 4; ++kk) {
            int k = k0 + kk;
            ulonglong2 bl = *(const ulonglong2*)&Bs[k * 128 + tx * 4];
            ulonglong2 bh = *(const ulonglong2*)&Bs[k * 128 + 64 + tx * 4];
            u64 bb0 = bl.x, bb1 = bl.y, bb2 = bh.x, bb3 = bh.y;
            #pragma unroll
            for (int mi = 0; mi < 8; ++mi) {
                float a_s = ((const float*)&av[mi])[kk];
                u64 aa; PACKDUP(aa, a_s);
                FMA2(acc[mi][0], aa, bb0);
                FMA2(acc[mi][1], aa, bb1);
                FMA2(acc[mi][2], aa, bb2);
                FMA2(acc[mi][3], aa, bb3);
            }
        }
    }

    #pragma unroll
    for (int mi = 0; mi < 8; ++mi) {
        int m = (mi < 4) ? (ty * 4 + mi) : (64 + ty * 4 + mi - 4);
        #pragma unroll
        for (int p = 0; p < 4; ++p) {
            int n = (p < 2) ? (tx * 4 + p * 2) : (64 + tx * 4 + (p - 2) * 2);
            float c0, c1; UNPACK2(c0, c1, acc[mi][p]);
            c0 = fmaxf(c0 + __ldg(&b1[n]), 0.f);
            c1 = fmaxf(c1 + __ldg(&b1[n + 1]), 0.f);
            __nv_bfloat16 h0 = __float2bfloat16(c0);
            __nv_bfloat16 h1 = __float2bfloat16(c1);
            __nv_bfloat16 l0 = __float2bfloat16(c0 - __bfloat162float(h0));
            __nv_bfloat16 l1 = __float2bfloat16(c1 - __bfloat162float(h1));
            size_t off = (size_t)(e0 + m) * HID + n;
            *(__nv_bfloat162*)&g_h_hi[off] = __nv_bfloat162(h0, h1);
            *(__nv_bfloat162*)&g_h_lo[off] = __nv_bfloat162(l0, l1);
        }
    }
}

// ============================================================
// K2: mma.sync split-bf16 GEMM -> tensor product -> scatter
// 512 threads, 16 warps: warp tile 32(edges) x 32(cols).
// ============================================================
__global__ __launch_bounds__(K2_THREADS, 1)
void k2_fused(const float* __restrict__ node_attr,
              const float* __restrict__ edge_sh,
              const float* __restrict__ b2,
              const long long* __restrict__ eidx) {
    extern __shared__ char smc[];
    uint32_t sb = smem_u32(smc);

    float* b2s = (float*)(smc + SB2S);
    float* sxs = (float*)(smc + SSXS);
    float* xsh = (float*)(smc + SXSH);
    float* dvv = (float*)(smc + SDVV);
    float* xvs = (float*)(smc + SXVS);
    float* svs = (float*)(smc + SSVS);
    int*  esrc = (int*)(smc + SESRC);
    float* Cs  = (float*)(smc + SCS);

    int tid = threadIdx.x;
    int wid = tid >> 5, lid = tid & 31;
    int e0 = blockIdx.x * 128;

    // ---- per-edge prep (threads 0..127) ----
    if (tid < 128) {
        int e = e0 + tid;
        int src, dst;
        if (g_idx32) {
            const int* e32 = (const int*)eidx;
            src = e32[e]; dst = e32[N_EDGES + e];
        } else {
            src = (int)eidx[e]; dst = (int)eidx[N_EDGES + e];
        }
        src = min(max(src, 0), N_NODES - 1);
        dst = min(max(dst, 0), N_NODES - 1);
        esrc[tid] = src;
        const float* na = node_attr + (size_t)dst * DD;
        float ss = edge_sh[(size_t)e * 4 + 0];
        float v0 = edge_sh[(size_t)e * 4 + 1];
        float v1 = edge_sh[(size_t)e * 4 + 2];
        float v2 = edge_sh[(size_t)e * 4 + 3];
        svs[tid * 3 + 0] = v0; svs[tid * 3 + 1] = v1; svs[tid * 3 + 2] = v2;
        #pragma unroll
        for (int i = 0; i < 32; ++i) {
            float x = na[i];
            xsh[tid * 32 + i] = x;
            sxs[tid * 32 + i] = x * ss;
        }
        #pragma unroll
        for (int i = 0; i < 8; ++i) {
            float a = na[32 + i * 3 + 0];
            float b = na[32 + i * 3 + 1];
            float c = na[32 + i * 3 + 2];
            xvs[tid * 24 + i * 3 + 0] = a * ss;
            xvs[tid * 24 + i * 3 + 1] = b * ss;
            xvs[tid * 24 + i * 3 + 2] = c * ss;
            dvv[tid * 8 + i] = (a * v0 + b * v1 + c * v2) * INV_SQRT3;
        }
    }

    // ---- load A tile (h hi/lo) once: [r][k], stride 272 B ----
    {
        const uint4* shi = (const uint4*)g_h_hi + (size_t)e0 * 16;  // 16 uint4/row
        const uint4* slo = (const uint4*)g_h_lo + (size_t)e0 * 16;
        for (int idx = tid; idx < 2048; idx += K2_THREADS) {
            int r = idx >> 4, c8 = idx & 15;
            int so = r * TSTRIDE + c8 * 16;
            *(uint4*)(smc + SA_HI + so) = shi[r * 16 + c8];
            *(uint4*)(smc + SA_LO + so) = slo[r * 16 + c8];
        }
    }

    // contraction mapping: 8 edge-groups of 16 edges
    int ct = tid & 63, eg = tid >> 6;   // eg in 0..7
    int vj = 0, vm = 0;
    if (ct >= 32) { int q = ct - 32; vj = q / 3; vm = q - vj * 3; }

    float tpreg[16];
    #pragma unroll
    for (int i = 0; i < 16; ++i) tpreg[i] = 0.f;

    // warp tile: rows mrow..mrow+31, cols ncol..ncol+31
    int mrow = (wid & 3) * 32;
    int ncol = (wid >> 2) * 32;
    int g = lid >> 2, t = lid & 3;

    // LDSM lane addressing
    int a_row = lid & 15;
    int a_koff = (lid & 16) ? 16 : 0;
    int b_n = (lid & 7) + ((lid & 16) ? 8 : 0);
    int b_koff = (lid & 8) ? 16 : 0;

    for (int nt = 0; nt < 13; ++nt) {
        int nb = nt * 128;
        __syncthreads();   // prev contraction done -> B/Cs region free

        // ---- load B tile (W2t rows nb..nb+127) hi/lo ----
        {
            const uint4* bhi = (const uint4*)g_W2t_hi + (size_t)nb * 16;
            const uint4* blo = (const uint4*)g_W2t_lo + (size_t)nb * 16;
            for (int idx = tid; idx < 2048; idx += K2_THREADS) {
                int r = idx >> 4, c8 = idx & 15;
                int so = r * TSTRIDE + c8 * 16;
                *(uint4*)(smc + SB_HI + so) = bhi[r * 16 + c8];
                *(uint4*)(smc + SB_LO + so) = blo[r * 16 + c8];
            }
        }
        if (tid < 128) b2s[tid] = (nb + tid < WN) ? b2[nb + tid] : 0.f;
        __syncthreads();

        // ---- GEMM: acc[2][4][4] over 3 split passes ----
        float acc[2][4][4];
        #pragma unroll
        for (int mt = 0; mt < 2; ++mt)
            #pragma unroll
            for (int j = 0; j < 4; ++j)
                #pragma unroll
                for (int q = 0; q < 4; ++q) acc[mt][j][q] = 0.f;

        const int pA[3] = {SA_HI, SA_HI, SA_LO};
        const int pB[3] = {SB_HI, SB_LO, SB_HI};
        #pragma unroll
        for (int p = 0; p < 3; ++p) {
            uint32_t aBase = sb + pA[p] + (mrow + a_row) * TSTRIDE + a_koff;
            uint32_t bBase = sb + pB[p] + (ncol + b_n) * TSTRIDE + b_koff;
            #pragma unroll
            for (int ks = 0; ks < 8; ++ks) {
                int k2b = ks * 32;   // 16 bf16 = 32 B per kstep
                uint32_t af[2][4];
                LDSM_X4(af[0][0], af[0][1], af[0][2], af[0][3], aBase + k2b);
                LDSM_X4(af[1][0], af[1][1], af[1][2], af[1][3], aBase + 16 * TSTRIDE + k2b);
                uint32_t bf[4][2];
                #pragma unroll
                for (int j2 = 0; j2 < 2; ++j2) {
                    uint32_t r0, r1, r2, r3;
                    LDSM_X4(r0, r1, r2, r3, bBase + j2 * 16 * TSTRIDE + k2b);
                    bf[j2 * 2][0] = r0; bf[j2 * 2][1] = r1;
                    bf[j2 * 2 + 1][0] = r2; bf[j2 * 2 + 1][1] = r3;
                }
                #pragma unroll
                for (int mt = 0; mt < 2; ++mt)
                    #pragma unroll
                    for (int j = 0; j < 4; ++j)
                        MMA_BF16(acc[mt][j], af[mt][0], af[mt][1], af[mt][2], af[mt][3],
                                 bf[j][0], bf[j][1]);
            }
        }
        __syncthreads();  // all warps done reading Bs

        // ---- epilogue: acc + b2 -> Cs ----
        #pragma unroll
        for (int mt = 0; mt < 2; ++mt) {
            int r0 = mrow + mt * 16 + g;
            #pragma unroll
            for (int j = 0; j < 4; ++j) {
                int c = ncol + j * 8 + 2 * t;
                Cs[r0 * CS_STRIDE + c]           = acc[mt][j][0] + b2s[c];
                Cs[r0 * CS_STRIDE + c + 1]       = acc[mt][j][1] + b2s[c + 1];
                Cs[(r0 + 8) * CS_STRIDE + c]     = acc[mt][j][2] + b2s[c];
                Cs[(r0 + 8) * CS_STRIDE + c + 1] = acc[mt][j][3] + b2s[c + 1];
            }
        }
        __syncthreads();

        // ---- contraction into tpreg (8 groups x 16 edges) ----
        if (ct < 32) {
            if (nt < 8) {                 // w_ss
                #pragma unroll
                for (int e = 0; e < 16; ++e) {
                    int ee = eg * 16 + e;
                    const float* cr = &Cs[ee * CS_STRIDE];
                    const float* co = &sxs[ee * 32 + nt * 4];
                    tpreg[e] += cr[ct] * co[0] + cr[32 + ct] * co[1]
                              + cr[64 + ct] * co[2] + cr[96 + ct] * co[3];
                }
            } else if (nt < 10) {         // w_vs
                #pragma unroll
                for (int e = 0; e < 16; ++e) {
                    int ee = eg * 16 + e;
                    const float* cr = &Cs[ee * CS_STRIDE];
                    const float* co = &dvv[ee * 8 + (nt - 8) * 4];
                    tpreg[e] += cr[ct] * co[0] + cr[32 + ct] * co[1]
                              + cr[64 + ct] * co[2] + cr[96 + ct] * co[3];
                }
            }
        } else if (ct < 56) {
            if (nt >= 10 && nt < 12) {    // w_sv
                int ib = (nt - 10) * 16;
                #pragma unroll
                for (int e = 0; e < 16; ++e) {
                    int ee = eg * 16 + e;
                    const float* cr = &Cs[ee * CS_STRIDE + vj];
                    const float* xr = &xsh[ee * 32 + ib];
                    float a2 = 0.f;
                    #pragma unroll
                    for (int ii = 0; ii < 16; ++ii) a2 += cr[ii * 8] * xr[ii];
                    tpreg[e] += a2 * svs[ee * 3 + vm];
                }
            } else if (nt == 12) {        // w_vv
                #pragma unroll
                for (int e = 0; e < 16; ++e) {
                    int ee = eg * 16 + e;
                    const float* cr = &Cs[ee * CS_STRIDE + vj];
                    const float* xr = &xvs[ee * 24 + vm];
                    float a2 = 0.f;
                    #pragma unroll
                    for (int ii = 0; ii < 8; ++ii) a2 += cr[ii * 8] * xr[ii * 3];
                    tpreg[e] += a2;
                }
            }
        }
    }

    // ---- scatter ----
    if (ct < 56) {
        #pragma unroll
        for (int e = 0; e < 16; ++e) {
            int s = esrc[eg * 16 + e];
            atomicAdd(&g_sums[(size_t)s * DD + ct], tpreg[e] * PATH_NORM);
        }
    } else if (ct == 56) {
        #pragma unroll
        for (int e = 0; e < 16; ++e)
            atomicAdd(&g_cnt[esrc[eg * 16 + e]], 1.0f);
    }
}

// ============================================================
// K4: pre = sums/max(cnt,1) + node_attr ; BN stats
// ============================================================
__global__ void k4_pre_stats(const float* __restrict__ node_attr) {
    __shared__ float bins[72];
    int tid = threadIdx.x;
    if (tid < 72) bins[tid] = 0.f;
    __syncthreads();
    int idx = blockIdx.x * 256 + tid;
    int n = idx / DD, f = idx - n * DD;
    float val = g_sums[idx] / fmaxf(g_cnt[n], 1.0f) + node_attr[idx];
    g_pre[idx] = val;
    if (f < NS) {
        atomicAdd(&bins[f], val);
        atomicAdd(&bins[32 + f], val * val);
    } else {
        atomicAdd(&bins[64 + (f - NS) / 3], val * val);
    }
    __syncthreads();
    if (tid < 72) atomicAdd(&g_stats[tid], bins[tid]);
}

// ============================================================
// K5: batch-norm finalize -> out
// ============================================================
__global__ void k5_norm(const float* __restrict__ gamma,
                        const float* __restrict__ beta,
                        float* __restrict__ out) {
    int idx = blockIdx.x * 256 + threadIdx.x;
    int f = idx % DD;
    float val = g_pre[idx];
    float o;
    if (f < NS) {
        float mean = g_stats[f] * (1.0f / N_NODES);
        float var  = g_stats[32 + f] * (1.0f / N_NODES) - mean * mean;
        o = (val - mean) * rsqrtf(var + EPS) * gamma[f] + beta[f];
    } else {
        int i = (f - NS) / 3;
        float vn2 = g_stats[64 + i] * (1.0f / N_NODES);
        o = val * rsqrtf(vn2 + EPS) * gamma[NS + i];
    }
    out[idx] = o;
}

// ============================================================
extern "C" void kernel_launch(void* const* d_in, const int* in_sizes, int n_in,
                              void* d_out, int out_size) {
    const float* node_attr = nullptr;
    const float* edge_attr = nullptr;
    const float* edge_sh   = nullptr;
    const float* W1 = nullptr;
    const float* b1 = nullptr;
    const float* W2 = nullptr;
    const float* b2 = nullptr;
    const float* gamma = nullptr;
    const float* beta  = nullptr;
    const long long* eidx = nullptr;

    for (int i = 0; i < n_in; ++i) {
        switch (in_sizes[i]) {
            case 917504:   node_attr = (const float*)d_in[i]; break;
            case 16777216: edge_attr = (const float*)d_in[i]; break;
            case 524288:   edge_sh   = (const float*)d_in[i]; break;
            case 16384:    W1 = (const float*)d_in[i]; break;
            case 128:      b1 = (const float*)d_in[i]; break;
            case 204800:   W2 = (const float*)d_in[i]; break;
            case 1600:     b2 = (const float*)d_in[i]; break;
            case 40:       gamma = (const float*)d_in[i]; break;
            case 32:       beta  = (const float*)d_in[i]; break;
            case 262144:   eidx = (const long long*)d_in[i]; break;
            default: break;
        }
    }
    float* out = (float*)d_out;
    (void)out_size;

    cudaFuncSetAttribute(k1_gemm_relu, cudaFuncAttributeMaxDynamicSharedMemorySize, 131072);
    cudaFuncSetAttribute(k2_fused,     cudaFuncAttributeMaxDynamicSharedMemorySize, K2_SMEM);

    k0_zero<<<3584, 256>>>(eidx);
    k_prep<<<(WNP * HID + 255) / 256, 256>>>(W2);
    k1_gemm_relu<<<N_EDGES / 128, 256, 131072>>>(edge_attr, W1, b1);
    k2_fused<<<N_EDGES / 128, K2_THREADS, K2_SMEM>>>(node_attr, edge_sh, b2, eidx);
    k4_pre_stats<<<(N_NODES * DD) / 256, 256>>>(node_attr);
    k5_norm<<<(N_NODES * DD) / 256, 256>>>(gamma, beta, out);
}

// round 16
// speedup vs baseline: 1.3980x; 1.3980x over previous
#include <cuda_runtime.h>
#include <cuda_bf16.h>
#include <cstdint>

#define NS 32
#define NV 8
#define N_NODES 16384
#define N_EDGES 131072
#define NEF 128
#define HID 128
#define WN 1600
#define DD 56
#define INV_SQRT3 0.57735026918962576451f
#define PATH_NORM 0.15811388300841897f /* 1/sqrt(40) */
#define EPS 1e-5f

// ---------------- scratch (static device globals) ----------------
__device__ __nv_bfloat16 g_h_hi[(size_t)N_EDGES * HID];   // 32 MB
__device__ __nv_bfloat16 g_h_lo[(size_t)N_EDGES * HID];   // 32 MB
__device__ __nv_bfloat16 g_W2t_hi[(size_t)1664 * HID];    // [c][k] (padded rows unused)
__device__ __nv_bfloat16 g_W2t_lo[(size_t)1664 * HID];
__device__ float g_sums[(size_t)N_NODES * DD];
__device__ float g_cnt[N_NODES];
__device__ float g_pre[(size_t)N_NODES * DD];
__device__ float g_stats[72];
__device__ int   g_idx32;

// ---------------- f32x2 helpers (K1 SGEMM) ----------------
#define PACKDUP(dst, s) do { unsigned _u = __float_as_uint(s); \
    asm("mov.b64 %0, {%1, %1};" : "=l"(dst) : "r"(_u)); } while (0)
#define FMA2(d, a, b) asm("fma.rn.f32x2 %0, %1, %2, %0;" : "+l"(d) : "l"(a), "l"(b))
#define UNPACK2(lo, hi, v) do { unsigned _lo, _hi; \
    asm("mov.b64 {%0, %1}, %2;" : "=r"(_lo), "=r"(_hi) : "l"(v)); \
    lo = __uint_as_float(_lo); hi = __uint_as_float(_hi); } while (0)

typedef unsigned long long u64;

__device__ __forceinline__ uint32_t smem_u32(const void* p) {
    uint32_t a;
    asm("{ .reg .u64 t; cvta.to.shared.u64 t, %1; cvt.u32.u64 %0, t; }" : "=r"(a) : "l"(p));
    return a;
}

#define LDSM_X4(r0, r1, r2, r3, addr) \
    asm volatile("ldmatrix.sync.aligned.m8n8.x4.shared.b16 {%0,%1,%2,%3}, [%4];" \
        : "=r"(r0), "=r"(r1), "=r"(r2), "=r"(r3) : "r"(addr))

#define MMA_BF16(c, a0, a1, a2, a3, b0, b1) \
    asm volatile("mma.sync.aligned.m16n8k16.row.col.f32.bf16.bf16.f32 " \
        "{%0,%1,%2,%3}, {%4,%5,%6,%7}, {%8,%9}, {%0,%1,%2,%3};" \
        : "+f"((c)[0]), "+f"((c)[1]), "+f"((c)[2]), "+f"((c)[3]) \
        : "r"(a0), "r"(a1), "r"(a2), "r"(a3), "r"(b0), "r"(b1))

#define CP_ASYNC16(dst, src) \
    asm volatile("cp.async.cg.shared.global [%0], [%1], 16;" :: "r"(dst), "l"(src))
#define CP_COMMIT() asm volatile("cp.async.commit_group;" ::: "memory")
#define CP_WAIT1()  asm volatile("cp.async.wait_group 1;" ::: "memory")
#define CP_WAIT0()  asm volatile("cp.async.wait_group 0;" ::: "memory")

// ---------------- K2 SMEM layout (byte offsets) ----------------
// A tiles: 128 rows x 136 bf16 (stride 272 B). B stages: 64 rows x 272 B per plane.
#define TSTRIDE 272
#define SA_HI 0
#define SA_LO 34816
#define SB0   69632          /* stage stride 34816; hi +0, lo +17408 */
#define SB_STAGE 34816
#define SB_LOPL  17408
#define SCS   139264         /* 128 x 68 floats = 34816 */
#define CS_STRIDE 68
#define SB2S  174080         /* 1664 floats */
#define SXSH  180736         /* 128 x 32 floats */
#define SDVV  197120         /* 128 x 8 */
#define SXVS  201216         /* 128 x 24 */
#define SSVS  213504         /* 128 x 3 */
#define SSSV  215040         /* 128 ss */
#define SESRC 215552         /* 128 int */
#define K2_SMEM 216064

#define NTILES 25            /* 1600 / 64 */

// ============================================================
// K0: zero accumulators + detect edge_index dtype
// ============================================================
__global__ void k0_zero(const long long* __restrict__ eidx) {
    int idx = blockIdx.x * 256 + threadIdx.x;
    if (idx < N_NODES * DD) g_sums[idx] = 0.f;
    if (idx < N_NODES)      g_cnt[idx]  = 0.f;
    if (idx < 72)           g_stats[idx] = 0.f;
    if (blockIdx.x == 0 && threadIdx.x == 0) {
        int is32 = 0;
        for (int i = 0; i < 64; ++i) {
            long long v = eidx[i];
            if (v < 0 || v >= N_NODES) { is32 = 1; break; }
        }
        g_idx32 = is32;
    }
}

// ============================================================
// K_prep: W2^T -> bf16 hi/lo planes  g_W2t[c][k]
// ============================================================
__global__ void k_prep(const float* __restrict__ W2) {
    int idx = blockIdx.x * 256 + threadIdx.x;
    if (idx >= 1664 * HID) return;
    int c = idx >> 7, k = idx & 127;
    float w = (c < WN) ? W2[(size_t)k * WN + c] : 0.f;
    __nv_bfloat16 hi = __float2bfloat16(w);
    float r = w - __bfloat162float(hi);
    g_W2t_hi[idx] = hi;
    g_W2t_lo[idx] = __float2bfloat16(r);
}

// ============================================================
// K1: h = relu(edge_attr @ W1 + b1) -> bf16 hi/lo planes
// ============================================================
__global__ __launch_bounds__(256, 1)
void k1_gemm_relu(const float* __restrict__ ea, const float* __restrict__ W1,
                  const float* __restrict__ b1) {
    extern __shared__ float sm[];
    float* As = sm;          // 128x128
    float* Bs = sm + 16384;  // 128x128
    int tid = threadIdx.x;
    int e0 = blockIdx.x * 128;

    for (int it = 0; it < 16; ++it) {
        int idx = tid + it * 256;
        int r = idx >> 5, c4 = idx & 31;
        *(float4*)&As[r * 128 + c4 * 4] = *(const float4*)&ea[(size_t)(e0 + r) * NEF + c4 * 4];
        *(float4*)&Bs[r * 128 + c4 * 4] = *(const float4*)&W1[(size_t)r * HID + c4 * 4];
    }
    __syncthreads();

    int tx = tid & 15, ty = tid >> 4;
    u64 acc[8][4];
    #pragma unroll
    for (int i = 0; i < 8; ++i)
        #pragma unroll
        for (int j = 0; j < 4; ++j) acc[i][j] = 0ull;

    #pragma unroll 2
    for (int k4 = 0; k4 < 32; ++k4) {
        int k0 = k4 * 4;
        float4 av[8];
        #pragma unroll
        for (int mi = 0; mi < 8; ++mi) {
            int m = (mi < 4) ? (ty * 4 + mi) : (64 + ty * 4 + mi - 4);
            av[mi] = *(const float4*)&As[m * 128 + k0];
        }
        #pragma unroll
        for (int kk = 0; kk < 4; ++kk) {
            int k = k0 + kk;
            ulonglong2 bl = *(const ulonglong2*)&Bs[k * 128 + tx * 4];
            ulonglong2 bh = *(const ulonglong2*)&Bs[k * 128 + 64 + tx * 4];
            u64 bb0 = bl.x, bb1 = bl.y, bb2 = bh.x, bb3 = bh.y;
            #pragma unroll
            for (int mi = 0; mi < 8; ++mi) {
                float a_s = ((const float*)&av[mi])[kk];
                u64 aa; PACKDUP(aa, a_s);
                FMA2(acc[mi][0], aa, bb0);
                FMA2(acc[mi][1], aa, bb1);
                FMA2(acc[mi][2], aa, bb2);
                FMA2(acc[mi][3], aa, bb3);
            }
        }
    }

    #pragma unroll
    for (int mi = 0; mi < 8; ++mi) {
        int m = (mi < 4) ? (ty * 4 + mi) : (64 + ty * 4 + mi - 4);
        #pragma unroll
        for (int p = 0; p < 4; ++p) {
            int n = (p < 2) ? (tx * 4 + p * 2) : (64 + tx * 4 + (p - 2) * 2);
            float c0, c1; UNPACK2(c0, c1, acc[mi][p]);
            c0 = fmaxf(c0 + __ldg(&b1[n]), 0.f);
            c1 = fmaxf(c1 + __ldg(&b1[n + 1]), 0.f);
            __nv_bfloat16 h0 = __float2bfloat16(c0);
            __nv_bfloat16 h1 = __float2bfloat16(c1);
            __nv_bfloat16 l0 = __float2bfloat16(c0 - __bfloat162float(h0));
            __nv_bfloat16 l1 = __float2bfloat16(c1 - __bfloat162float(h1));
            size_t off = (size_t)(e0 + m) * HID + n;
            *(__nv_bfloat162*)&g_h_hi[off] = __nv_bfloat162(h0, h1);
            *(__nv_bfloat162*)&g_h_lo[off] = __nv_bfloat162(l0, l1);
        }
    }
}

// ============================================================
// K2: mma.sync split-bf16 GEMM -> tensor product -> scatter
// 256 threads, 8 warps; N-tile=64 (25 tiles), cp.async double-buffered B.
// Warp tile 32(edges) x 32(cols).
// ============================================================
__global__ __launch_bounds__(256, 1)
void k2_fused(const float* __restrict__ node_attr,
              const float* __restrict__ edge_sh,
              const float* __restrict__ b2,
              const long long* __restrict__ eidx) {
    extern __shared__ char smc[];
    uint32_t sb = smem_u32(smc);

    float* b2s = (float*)(smc + SB2S);
    float* xsh = (float*)(smc + SXSH);
    float* dvv = (float*)(smc + SDVV);
    float* xvs = (float*)(smc + SXVS);
    float* svs = (float*)(smc + SSVS);
    float* ssv = (float*)(smc + SSSV);
    int*  esrc = (int*)(smc + SESRC);
    float* Cs  = (float*)(smc + SCS);

    int tid = threadIdx.x;
    int wid = tid >> 5, lid = tid & 31;
    int e0 = blockIdx.x * 128;

    // ---- prefetch B tile 0 (cp.async) ----
    {
        uint32_t dstb = sb + SB0;   // stage 0
        for (int idx = tid; idx < 2048; idx += 256) {
            int plane = idx >> 10, rem = idx & 1023;
            int r = rem >> 4, c8 = rem & 15;
            const __nv_bfloat16* src = (plane ? g_W2t_lo : g_W2t_hi)
                                       + (size_t)r * HID + c8 * 8;
            CP_ASYNC16(dstb + plane * SB_LOPL + r * TSTRIDE + c8 * 16, src);
        }
        CP_COMMIT();
    }

    // ---- per-edge prep (threads 0..127) ----
    if (tid < 128) {
        int e = e0 + tid;
        int src, dst;
        if (g_idx32) {
            const int* e32 = (const int*)eidx;
            src = e32[e]; dst = e32[N_EDGES + e];
        } else {
            src = (int)eidx[e]; dst = (int)eidx[N_EDGES + e];
        }
        src = min(max(src, 0), N_NODES - 1);
        dst = min(max(dst, 0), N_NODES - 1);
        esrc[tid] = src;
        const float* na = node_attr + (size_t)dst * DD;
        float ss = edge_sh[(size_t)e * 4 + 0];
        float v0 = edge_sh[(size_t)e * 4 + 1];
        float v1 = edge_sh[(size_t)e * 4 + 2];
        float v2 = edge_sh[(size_t)e * 4 + 3];
        ssv[tid] = ss;
        svs[tid * 3 + 0] = v0; svs[tid * 3 + 1] = v1; svs[tid * 3 + 2] = v2;
        #pragma unroll
        for (int i = 0; i < 32; ++i) xsh[tid * 32 + i] = na[i];
        #pragma unroll
        for (int i = 0; i < 8; ++i) {
            float a = na[32 + i * 3 + 0];
            float b = na[32 + i * 3 + 1];
            float c = na[32 + i * 3 + 2];
            xvs[tid * 24 + i * 3 + 0] = a * ss;
            xvs[tid * 24 + i * 3 + 1] = b * ss;
            xvs[tid * 24 + i * 3 + 2] = c * ss;
            dvv[tid * 8 + i] = (a * v0 + b * v1 + c * v2) * INV_SQRT3;
        }
    }

    // ---- b2 preload (all 1600, zero-pad to 1664) ----
    for (int idx = tid; idx < 1664; idx += 256)
        b2s[idx] = (idx < WN) ? b2[idx] : 0.f;

    // ---- load A tile (h hi/lo) once: [r][k], stride 272 B ----
    {
        const uint4* shi = (const uint4*)g_h_hi + (size_t)e0 * 16;
        const uint4* slo = (const uint4*)g_h_lo + (size_t)e0 * 16;
        for (int idx = tid; idx < 2048; idx += 256) {
            int r = idx >> 4, c8 = idx & 15;
            int so = r * TSTRIDE + c8 * 16;
            *(uint4*)(smc + SA_HI + so) = shi[r * 16 + c8];
            *(uint4*)(smc + SA_LO + so) = slo[r * 16 + c8];
        }
    }

    int ct = tid & 63, eg = tid >> 6;   // eg 0..3, 32 edges each
    int vj = 0, vm = 0;
    if (ct >= 32) { int q = ct - 32; vj = q / 3; vm = q - vj * 3; }

    float tpreg[32];
    #pragma unroll
    for (int i = 0; i < 32; ++i) tpreg[i] = 0.f;

    // warp tile: rows mrow..mrow+31, cols ncol..ncol+31 (of 64)
    int mrow = (wid & 3) * 32;
    int ncol = (wid >> 2) * 32;
    int g = lid >> 2, t = lid & 3;

    int a_row = lid & 15;
    int a_koff = (lid & 16) ? 16 : 0;
    int b_n = (lid & 7) + ((lid & 16) ? 8 : 0);
    int b_koff = (lid & 8) ? 16 : 0;

    for (int nt = 0; nt < NTILES; ++nt) {
        // ---- prefetch B tile nt+1 into other stage ----
        if (nt + 1 < NTILES) {
            uint32_t dstb = sb + SB0 + ((nt + 1) & 1) * SB_STAGE;
            size_t rowbase = (size_t)(nt + 1) * 64;
            for (int idx = tid; idx < 2048; idx += 256) {
                int plane = idx >> 10, rem = idx & 1023;
                int r = rem >> 4, c8 = rem & 15;
                const __nv_bfloat16* src = (plane ? g_W2t_lo : g_W2t_hi)
                                           + (rowbase + r) * HID + c8 * 8;
                CP_ASYNC16(dstb + plane * SB_LOPL + r * TSTRIDE + c8 * 16, src);
            }
            CP_COMMIT();
            CP_WAIT1();   // tile nt complete
        } else {
            CP_COMMIT();  // empty group keeps counts consistent
            CP_WAIT0();
        }
        __syncthreads();  // B(nt) visible to all; Cs free (contraction nt-1 done)

        uint32_t bStage = sb + SB0 + (nt & 1) * SB_STAGE;

        // ---- GEMM: acc[2][4][4] over 3 split passes ----
        float acc[2][4][4];
        #pragma unroll
        for (int mt = 0; mt < 2; ++mt)
            #pragma unroll
            for (int j = 0; j < 4; ++j)
                #pragma unroll
                for (int q = 0; q < 4; ++q) acc[mt][j][q] = 0.f;

        const int pAoff[3] = {SA_HI, SA_HI, SA_LO};
        const int pBoff[3] = {0, SB_LOPL, 0};
        #pragma unroll
        for (int p = 0; p < 3; ++p) {
            uint32_t aBase = sb + pAoff[p] + (mrow + a_row) * TSTRIDE + a_koff;
            uint32_t bBase = bStage + pBoff[p] + (ncol + b_n) * TSTRIDE + b_koff;
            #pragma unroll
            for (int ks = 0; ks < 8; ++ks) {
                int k2b = ks * 32;
                uint32_t af[2][4];
                LDSM_X4(af[0][0], af[0][1], af[0][2], af[0][3], aBase + k2b);
                LDSM_X4(af[1][0], af[1][1], af[1][2], af[1][3], aBase + 16 * TSTRIDE + k2b);
                uint32_t bf[4][2];
                {
                    uint32_t r0, r1, r2, r3;
                    LDSM_X4(r0, r1, r2, r3, bBase + k2b);
                    bf[0][0] = r0; bf[0][1] = r1; bf[1][0] = r2; bf[1][1] = r3;
                    LDSM_X4(r0, r1, r2, r3, bBase + 16 * TSTRIDE + k2b);
                    bf[2][0] = r0; bf[2][1] = r1; bf[3][0] = r2; bf[3][1] = r3;
                }
                #pragma unroll
                for (int mt = 0; mt < 2; ++mt)
                    #pragma unroll
                    for (int j = 0; j < 4; ++j)
                        MMA_BF16(acc[mt][j], af[mt][0], af[mt][1], af[mt][2], af[mt][3],
                                 bf[j][0], bf[j][1]);
            }
        }
        __syncthreads();  // GEMM(nt) done -> Cs writable

        // ---- epilogue: acc + b2 -> Cs (local cols 0..63) ----
        int nb = nt * 64;
        #pragma unroll
        for (int mt = 0; mt < 2; ++mt) {
            int r0 = mrow + mt * 16 + g;
            #pragma unroll
            for (int j = 0; j < 4; ++j) {
                int c = ncol + j * 8 + 2 * t;
                Cs[r0 * CS_STRIDE + c]           = acc[mt][j][0] + b2s[nb + c];
                Cs[r0 * CS_STRIDE + c + 1]       = acc[mt][j][1] + b2s[nb + c + 1];
                Cs[(r0 + 8) * CS_STRIDE + c]     = acc[mt][j][2] + b2s[nb + c];
                Cs[(r0 + 8) * CS_STRIDE + c + 1] = acc[mt][j][3] + b2s[nb + c + 1];
            }
        }
        __syncthreads();

        // ---- contraction into tpreg ----
        if (ct < 32) {
            if (nt < 16) {                // w_ss: i0 = nt*2
                int i0 = nt * 2;
                #pragma unroll
                for (int e = 0; e < 32; ++e) {
                    int ee = eg * 32 + e;
                    const float* cr = &Cs[ee * CS_STRIDE];
                    float ss = ssv[ee];
                    float co0 = xsh[ee * 32 + i0] * ss;
                    float co1 = xsh[ee * 32 + i0 + 1] * ss;
                    tpreg[e] += cr[ct] * co0 + cr[32 + ct] * co1;
                }
            } else if (nt < 20) {         // w_vs: iv0 = (nt-16)*2
                int iv0 = (nt - 16) * 2;
                #pragma unroll
                for (int e = 0; e < 32; ++e) {
                    int ee = eg * 32 + e;
                    const float* cr = &Cs[ee * CS_STRIDE];
                    const float* co = &dvv[ee * 8 + iv0];
                    tpreg[e] += cr[ct] * co[0] + cr[32 + ct] * co[1];
                }
            }
        } else if (ct < 56) {
            if (nt >= 20 && nt < 24) {    // w_sv: ib = (nt-20)*8
                int ib = (nt - 20) * 8;
                #pragma unroll
                for (int e = 0; e < 32; ++e) {
                    int ee = eg * 32 + e;
                    const float* cr = &Cs[ee * CS_STRIDE + vj];
                    const float* xr = &xsh[ee * 32 + ib];
                    float a2 = 0.f;
                    #pragma unroll
                    for (int ii = 0; ii < 8; ++ii) a2 += cr[ii * 8] * xr[ii];
                    tpreg[e] += a2 * svs[ee * 3 + vm];
                }
            } else if (nt == 24) {        // w_vv
                #pragma unroll
                for (int e = 0; e < 32; ++e) {
                    int ee = eg * 32 + e;
                    const float* cr = &Cs[ee * CS_STRIDE + vj];
                    const float* xr = &xvs[ee * 24 + vm];
                    float a2 = 0.f;
                    #pragma unroll
                    for (int ii = 0; ii < 8; ++ii) a2 += cr[ii * 8] * xr[ii * 3];
                    tpreg[e] += a2;
                }
            }
        }
    }

    // ---- scatter ----
    if (ct < 56) {
        #pragma unroll
        for (int e = 0; e < 32; ++e) {
            int s = esrc[eg * 32 + e];
            atomicAdd(&g_sums[(size_t)s * DD + ct], tpreg[e] * PATH_NORM);
        }
    } else if (ct == 56) {
        #pragma unroll
        for (int e = 0; e < 32; ++e)
            atomicAdd(&g_cnt[esrc[eg * 32 + e]], 1.0f);
    }
}

// ============================================================
// K4: pre = sums/max(cnt,1) + node_attr ; BN stats
// ============================================================
__global__ void k4_pre_stats(const float* __restrict__ node_attr) {
    __shared__ float bins[72];
    int tid = threadIdx.x;
    if (tid < 72) bins[tid] = 0.f;
    __syncthreads();
    int idx = blockIdx.x * 256 + tid;
    int n = idx / DD, f = idx - n * DD;
    float val = g_sums[idx] / fmaxf(g_cnt[n], 1.0f) + node_attr[idx];
    g_pre[idx] = val;
    if (f < NS) {
        atomicAdd(&bins[f], val);
        atomicAdd(&bins[32 + f], val * val);
    } else {
        atomicAdd(&bins[64 + (f - NS) / 3], val * val);
    }
    __syncthreads();
    if (tid < 72) atomicAdd(&g_stats[tid], bins[tid]);
}

// ============================================================
// K5: batch-norm finalize -> out
// ============================================================
__global__ void k5_norm(const float* __restrict__ gamma,
                        const float* __restrict__ beta,
                        float* __restrict__ out) {
    int idx = blockIdx.x * 256 + threadIdx.x;
    int f = idx % DD;
    float val = g_pre[idx];
    float o;
    if (f < NS) {
        float mean = g_stats[f] * (1.0f / N_NODES);
        float var  = g_stats[32 + f] * (1.0f / N_NODES) - mean * mean;
        o = (val - mean) * rsqrtf(var + EPS) * gamma[f] + beta[f];
    } else {
        int i = (f - NS) / 3;
        float vn2 = g_stats[64 + i] * (1.0f / N_NODES);
        o = val * rsqrtf(vn2 + EPS) * gamma[NS + i];
    }
    out[idx] = o;
}

// ============================================================
extern "C" void kernel_launch(void* const* d_in, const int* in_sizes, int n_in,
                              void* d_out, int out_size) {
    const float* node_attr = nullptr;
    const float* edge_attr = nullptr;
    const float* edge_sh   = nullptr;
    const float* W1 = nullptr;
    const float* b1 = nullptr;
    const float* W2 = nullptr;
    const float* b2 = nullptr;
    const float* gamma = nullptr;
    const float* beta  = nullptr;
    const long long* eidx = nullptr;

    for (int i = 0; i < n_in; ++i) {
        switch (in_sizes[i]) {
            case 917504:   node_attr = (const float*)d_in[i]; break;
            case 16777216: edge_attr = (const float*)d_in[i]; break;
            case 524288:   edge_sh   = (const float*)d_in[i]; break;
            case 16384:    W1 = (const float*)d_in[i]; break;
            case 128:      b1 = (const float*)d_in[i]; break;
            case 204800:   W2 = (const float*)d_in[i]; break;
            case 1600:     b2 = (const float*)d_in[i]; break;
            case 40:       gamma = (const float*)d_in[i]; break;
            case 32:       beta  = (const float*)d_in[i]; break;
            case 262144:   eidx = (const long long*)d_in[i]; break;
            default: break;
        }
    }
    float* out = (float*)d_out;
    (void)out_size;

    cudaFuncSetAttribute(k1_gemm_relu, cudaFuncAttributeMaxDynamicSharedMemorySize, 131072);
    cudaFuncSetAttribute(k2_fused,     cudaFuncAttributeMaxDynamicSharedMemorySize, K2_SMEM);

    k0_zero<<<3584, 256>>>(eidx);
    k_prep<<<(1664 * HID + 255) / 256, 256>>>(W2);
    k1_gemm_relu<<<N_EDGES / 128, 256, 131072>>>(edge_attr, W1, b1);
    k2_fused<<<N_EDGES / 128, 256, K2_SMEM>>>(node_attr, edge_sh, b2, eidx);
    k4_pre_stats<<<(N_NODES * DD) / 256, 256>>>(node_attr);
    k5_norm<<<(N_NODES * DD) / 256, 256>>>(gamma, beta, out);
}

// round 17
// speedup vs baseline: 1.7026x; 1.2178x over previous
#include <cuda_runtime.h>
#include <cuda_bf16.h>
#include <cstdint>

#define NS 32
#define NV 8
#define N_NODES 16384
#define N_EDGES 131072
#define NEF 128
#define HID 128
#define WN 1600
#define DD 56
#define INV_SQRT3 0.57735026918962576451f
#define PATH_NORM 0.15811388300841897f /* 1/sqrt(40) */
#define EPS 1e-5f

// ---------------- scratch (static device globals) ----------------
__device__ __nv_bfloat16 g_h_hi[(size_t)N_EDGES * HID];   // 32 MB
__device__ __nv_bfloat16 g_h_lo[(size_t)N_EDGES * HID];   // 32 MB
__device__ __nv_bfloat16 g_W2t_hi[(size_t)1664 * HID];    // [c][k] (padded rows unused)
__device__ __nv_bfloat16 g_W2t_lo[(size_t)1664 * HID];
__device__ float g_sums[(size_t)N_NODES * DD];
__device__ float g_cnt[N_NODES];
__device__ float g_pre[(size_t)N_NODES * DD];
__device__ float g_stats[72];
__device__ int   g_idx32;

// ---------------- f32x2 helpers (K1 SGEMM) ----------------
#define PACKDUP(dst, s) do { unsigned _u = __float_as_uint(s); \
    asm("mov.b64 %0, {%1, %1};" : "=l"(dst) : "r"(_u)); } while (0)
#define FMA2(d, a, b) asm("fma.rn.f32x2 %0, %1, %2, %0;" : "+l"(d) : "l"(a), "l"(b))
#define UNPACK2(lo, hi, v) do { unsigned _lo, _hi; \
    asm("mov.b64 {%0, %1}, %2;" : "=r"(_lo), "=r"(_hi) : "l"(v)); \
    lo = __uint_as_float(_lo); hi = __uint_as_float(_hi); } while (0)

typedef unsigned long long u64;

__device__ __forceinline__ uint32_t smem_u32(const void* p) {
    uint32_t a;
    asm("{ .reg .u64 t; cvta.to.shared.u64 t, %1; cvt.u32.u64 %0, t; }" : "=r"(a) : "l"(p));
    return a;
}

#define LDSM_X4(r0, r1, r2, r3, addr) \
    asm volatile("ldmatrix.sync.aligned.m8n8.x4.shared.b16 {%0,%1,%2,%3}, [%4];" \
        : "=r"(r0), "=r"(r1), "=r"(r2), "=r"(r3) : "r"(addr))

#define MMA_BF16(c, a0, a1, a2, a3, b0, b1) \
    asm volatile("mma.sync.aligned.m16n8k16.row.col.f32.bf16.bf16.f32 " \
        "{%0,%1,%2,%3}, {%4,%5,%6,%7}, {%8,%9}, {%0,%1,%2,%3};" \
        : "+f"((c)[0]), "+f"((c)[1]), "+f"((c)[2]), "+f"((c)[3]) \
        : "r"(a0), "r"(a1), "r"(a2), "r"(a3), "r"(b0), "r"(b1))

#define CP_ASYNC16(dst, src) \
    asm volatile("cp.async.cg.shared.global [%0], [%1], 16;" :: "r"(dst), "l"(src))
#define CP_COMMIT() asm volatile("cp.async.commit_group;" ::: "memory")
#define CP_WAIT0()  asm volatile("cp.async.wait_group 0;" ::: "memory")

// ---------------- K2 SMEM layout (byte offsets) ----------------
// A tiles: 128 rows x 136 bf16 (stride 272 B). B stages: 64 rows x 272 B per plane.
#define TSTRIDE 272
#define SA_HI 0
#define SA_LO 34816
#define SB0   69632          /* 2 stages x 34816; hi +0, lo +17408 within stage */
#define SB_STAGE 34816
#define SB_LOPL  17408
#define SB2S  139264         /* 1664 floats = 6656 B */
#define SSXS  145920         /* 128 x 32 floats (xs*ss) */
#define SXSH  162304         /* 128 x 32 floats (xs raw) */
#define SDVV  178688         /* 128 x 8 */
#define SXVS  182784         /* 128 x 24 (xv*ss) */
#define SSVS  195072         /* 128 x 3 (sv) */
#define SESRC 196608         /* 128 int */
#define K2_SMEM 197120

#define NTILES 25            /* 1600 / 64 */

// ============================================================
// K0: zero accumulators + detect edge_index dtype
// ============================================================
__global__ void k0_zero(const long long* __restrict__ eidx) {
    int idx = blockIdx.x * 256 + threadIdx.x;
    if (idx < N_NODES * DD) g_sums[idx] = 0.f;
    if (idx < N_NODES)      g_cnt[idx]  = 0.f;
    if (idx < 72)           g_stats[idx] = 0.f;
    if (blockIdx.x == 0 && threadIdx.x == 0) {
        int is32 = 0;
        for (int i = 0; i < 64; ++i) {
            long long v = eidx[i];
            if (v < 0 || v >= N_NODES) { is32 = 1; break; }
        }
        g_idx32 = is32;
    }
}

// ============================================================
// K_prep: W2^T -> bf16 hi/lo planes  g_W2t[c][k]
// ============================================================
__global__ void k_prep(const float* __restrict__ W2) {
    int idx = blockIdx.x * 256 + threadIdx.x;
    if (idx >= 1664 * HID) return;
    int c = idx >> 7, k = idx & 127;
    float w = (c < WN) ? W2[(size_t)k * WN + c] : 0.f;
    __nv_bfloat16 hi = __float2bfloat16(w);
    float r = w - __bfloat162float(hi);
    g_W2t_hi[idx] = hi;
    g_W2t_lo[idx] = __float2bfloat16(r);
}

// ============================================================
// K1: h = relu(edge_attr @ W1 + b1) -> bf16 hi/lo planes
// ============================================================
__global__ __launch_bounds__(256, 1)
void k1_gemm_relu(const float* __restrict__ ea, const float* __restrict__ W1,
                  const float* __restrict__ b1) {
    extern __shared__ float sm[];
    float* As = sm;          // 128x128
    float* Bs = sm + 16384;  // 128x128
    int tid = threadIdx.x;
    int e0 = blockIdx.x * 128;

    for (int it = 0; it < 16; ++it) {
        int idx = tid + it * 256;
        int r = idx >> 5, c4 = idx & 31;
        *(float4*)&As[r * 128 + c4 * 4] = *(const float4*)&ea[(size_t)(e0 + r) * NEF + c4 * 4];
        *(float4*)&Bs[r * 128 + c4 * 4] = *(const float4*)&W1[(size_t)r * HID + c4 * 4];
    }
    __syncthreads();

    int tx = tid & 15, ty = tid >> 4;
    u64 acc[8][4];
    #pragma unroll
    for (int i = 0; i < 8; ++i)
        #pragma unroll
        for (int j = 0; j < 4; ++j) acc[i][j] = 0ull;

    #pragma unroll 2
    for (int k4 = 0; k4 < 32; ++k4) {
        int k0 = k4 * 4;
        float4 av[8];
        #pragma unroll
        for (int mi = 0; mi < 8; ++mi) {
            int m = (mi < 4) ? (ty * 4 + mi) : (64 + ty * 4 + mi - 4);
            av[mi] = *(const float4*)&As[m * 128 + k0];
        }
        #pragma unroll
        for (int kk = 0; kk < 4; ++kk) {
            int k = k0 + kk;
            ulonglong2 bl = *(const ulonglong2*)&Bs[k * 128 + tx * 4];
            ulonglong2 bh = *(const ulonglong2*)&Bs[k * 128 + 64 + tx * 4];
            u64 bb0 = bl.x, bb1 = bl.y, bb2 = bh.x, bb3 = bh.y;
            #pragma unroll
            for (int mi = 0; mi < 8; ++mi) {
                float a_s = ((const float*)&av[mi])[kk];
                u64 aa; PACKDUP(aa, a_s);
                FMA2(acc[mi][0], aa, bb0);
                FMA2(acc[mi][1], aa, bb1);
                FMA2(acc[mi][2], aa, bb2);
                FMA2(acc[mi][3], aa, bb3);
            }
        }
    }

    #pragma unroll
    for (int mi = 0; mi < 8; ++mi) {
        int m = (mi < 4) ? (ty * 4 + mi) : (64 + ty * 4 + mi - 4);
        #pragma unroll
        for (int p = 0; p < 4; ++p) {
            int n = (p < 2) ? (tx * 4 + p * 2) : (64 + tx * 4 + (p - 2) * 2);
            float c0, c1; UNPACK2(c0, c1, acc[mi][p]);
            c0 = fmaxf(c0 + __ldg(&b1[n]), 0.f);
            c1 = fmaxf(c1 + __ldg(&b1[n + 1]), 0.f);
            __nv_bfloat16 h0 = __float2bfloat16(c0);
            __nv_bfloat16 h1 = __float2bfloat16(c1);
            __nv_bfloat16 l0 = __float2bfloat16(c0 - __bfloat162float(h0));
            __nv_bfloat16 l1 = __float2bfloat16(c1 - __bfloat162float(h1));
            size_t off = (size_t)(e0 + m) * HID + n;
            *(__nv_bfloat162*)&g_h_hi[off] = __nv_bfloat162(h0, h1);
            *(__nv_bfloat162*)&g_h_lo[off] = __nv_bfloat162(l0, l1);
        }
    }
}

// ============================================================
// K2: mma.sync split-bf16 GEMM with IN-REGISTER tensor-product
// contraction (no C staging) -> atomic scatter.
// 256 threads, 8 warps; warp tile 32(edges) x 32(cols of 64).
// ============================================================
__global__ __launch_bounds__(256, 1)
void k2_fused(const float* __restrict__ node_attr,
              const float* __restrict__ edge_sh,
              const float* __restrict__ b2,
              const long long* __restrict__ eidx) {
    extern __shared__ char smc[];
    uint32_t sb = smem_u32(smc);

    float* b2s = (float*)(smc + SB2S);
    float* sxs = (float*)(smc + SSXS);
    float* xsh = (float*)(smc + SXSH);
    float* dvv = (float*)(smc + SDVV);
    float* xvs = (float*)(smc + SXVS);
    float* svs = (float*)(smc + SSVS);
    int*  esrc = (int*)(smc + SESRC);

    int tid = threadIdx.x;
    int wid = tid >> 5, lid = tid & 31;
    int e0 = blockIdx.x * 128;

    // ---- prefetch B tile 0 (cp.async) ----
    {
        uint32_t dstb = sb + SB0;   // stage 0
        for (int idx = tid; idx < 2048; idx += 256) {
            int plane = idx >> 10, rem = idx & 1023;
            int r = rem >> 4, c8 = rem & 15;
            const __nv_bfloat16* src = (plane ? g_W2t_lo : g_W2t_hi)
                                       + (size_t)r * HID + c8 * 8;
            CP_ASYNC16(dstb + plane * SB_LOPL + r * TSTRIDE + c8 * 16, src);
        }
        CP_COMMIT();
    }

    // ---- per-edge prep (threads 0..127) ----
    if (tid < 128) {
        int e = e0 + tid;
        int src, dst;
        if (g_idx32) {
            const int* e32 = (const int*)eidx;
            src = e32[e]; dst = e32[N_EDGES + e];
        } else {
            src = (int)eidx[e]; dst = (int)eidx[N_EDGES + e];
        }
        src = min(max(src, 0), N_NODES - 1);
        dst = min(max(dst, 0), N_NODES - 1);
        esrc[tid] = src;
        const float* na = node_attr + (size_t)dst * DD;
        float ss = edge_sh[(size_t)e * 4 + 0];
        float v0 = edge_sh[(size_t)e * 4 + 1];
        float v1 = edge_sh[(size_t)e * 4 + 2];
        float v2 = edge_sh[(size_t)e * 4 + 3];
        svs[tid * 3 + 0] = v0; svs[tid * 3 + 1] = v1; svs[tid * 3 + 2] = v2;
        #pragma unroll
        for (int i = 0; i < 32; ++i) {
            float x = na[i];
            xsh[tid * 32 + i] = x;
            sxs[tid * 32 + i] = x * ss;
        }
        #pragma unroll
        for (int i = 0; i < 8; ++i) {
            float a = na[32 + i * 3 + 0];
            float b = na[32 + i * 3 + 1];
            float c = na[32 + i * 3 + 2];
            xvs[tid * 24 + i * 3 + 0] = a * ss;
            xvs[tid * 24 + i * 3 + 1] = b * ss;
            xvs[tid * 24 + i * 3 + 2] = c * ss;
            dvv[tid * 8 + i] = (a * v0 + b * v1 + c * v2) * INV_SQRT3;
        }
    }

    // ---- b2 preload ----
    for (int idx = tid; idx < 1664; idx += 256)
        b2s[idx] = (idx < WN) ? b2[idx] : 0.f;

    // ---- load A tile (h hi/lo) once: [r][k], stride 272 B ----
    {
        const uint4* shi = (const uint4*)g_h_hi + (size_t)e0 * 16;
        const uint4* slo = (const uint4*)g_h_lo + (size_t)e0 * 16;
        for (int idx = tid; idx < 2048; idx += 256) {
            int r = idx >> 4, c8 = idx & 15;
            int so = r * TSTRIDE + c8 * 16;
            *(uint4*)(smc + SA_HI + so) = shi[r * 16 + c8];
            *(uint4*)(smc + SA_LO + so) = slo[r * 16 + c8];
        }
    }

    // warp tile: rows mrow..mrow+31 (edges), cols ncol..ncol+31 (of 64)
    int mrow = (wid & 3) * 32;
    int ncol = (wid >> 2) * 32;
    int g = lid >> 2, t = lid & 3;

    int a_row = lid & 15;
    int a_koff = (lid & 16) ? 16 : 0;
    int b_n = (lid & 7) + ((lid & 16) ? 8 : 0);
    int b_koff = (lid & 8) ? 16 : 0;

    // per-lane rows: [mt][rh]
    int rows_[2][2];
    rows_[0][0] = mrow + g;      rows_[0][1] = mrow + g + 8;
    rows_[1][0] = mrow + 16 + g; rows_[1][1] = mrow + 24 + g;

    // scalar partials (same shape as acc) + vector a2 partials
    float sp[2][4][4];
    #pragma unroll
    for (int mt = 0; mt < 2; ++mt)
        #pragma unroll
        for (int j = 0; j < 4; ++j)
            #pragma unroll
            for (int q = 0; q < 4; ++q) sp[mt][j][q] = 0.f;
    float a2[2][2][2];
    #pragma unroll
    for (int mt = 0; mt < 2; ++mt)
        #pragma unroll
        for (int rh = 0; rh < 2; ++rh)
            #pragma unroll
            for (int re = 0; re < 2; ++re) a2[mt][rh][re] = 0.f;

    for (int nt = 0; nt < NTILES; ++nt) {
        CP_WAIT0();
        __syncthreads();   // B(nt) visible; prev GEMM done (stage safe); prep visible (nt==0)

        // ---- prefetch B tile nt+1 into other stage ----
        if (nt + 1 < NTILES) {
            uint32_t dstb = sb + SB0 + ((nt + 1) & 1) * SB_STAGE;
            size_t rowbase = (size_t)(nt + 1) * 64;
            for (int idx = tid; idx < 2048; idx += 256) {
                int plane = idx >> 10, rem = idx & 1023;
                int r = rem >> 4, c8 = rem & 15;
                const __nv_bfloat16* src = (plane ? g_W2t_lo : g_W2t_hi)
                                           + (rowbase + r) * HID + c8 * 8;
                CP_ASYNC16(dstb + plane * SB_LOPL + r * TSTRIDE + c8 * 16, src);
            }
            CP_COMMIT();
        }

        uint32_t bStage = sb + SB0 + (nt & 1) * SB_STAGE;

        // ---- GEMM: acc[2][4][4] over 3 split passes ----
        float acc[2][4][4];
        #pragma unroll
        for (int mt = 0; mt < 2; ++mt)
            #pragma unroll
            for (int j = 0; j < 4; ++j)
                #pragma unroll
                for (int q = 0; q < 4; ++q) acc[mt][j][q] = 0.f;

        const int pAoff[3] = {SA_HI, SA_HI, SA_LO};
        const int pBoff[3] = {0, SB_LOPL, 0};
        #pragma unroll
        for (int p = 0; p < 3; ++p) {
            uint32_t aBase = sb + pAoff[p] + (mrow + a_row) * TSTRIDE + a_koff;
            uint32_t bBase = bStage + pBoff[p] + (ncol + b_n) * TSTRIDE + b_koff;
            #pragma unroll
            for (int ks = 0; ks < 8; ++ks) {
                int k2b = ks * 32;
                uint32_t af[2][4];
                LDSM_X4(af[0][0], af[0][1], af[0][2], af[0][3], aBase + k2b);
                LDSM_X4(af[1][0], af[1][1], af[1][2], af[1][3], aBase + 16 * TSTRIDE + k2b);
                uint32_t bf[4][2];
                {
                    uint32_t r0, r1, r2, r3;
                    LDSM_X4(r0, r1, r2, r3, bBase + k2b);
                    bf[0][0] = r0; bf[0][1] = r1; bf[1][0] = r2; bf[1][1] = r3;
                    LDSM_X4(r0, r1, r2, r3, bBase + 16 * TSTRIDE + k2b);
                    bf[2][0] = r0; bf[2][1] = r1; bf[3][0] = r2; bf[3][1] = r3;
                }
                #pragma unroll
                for (int mt = 0; mt < 2; ++mt)
                    #pragma unroll
                    for (int j = 0; j < 4; ++j)
                        MMA_BF16(acc[mt][j], af[mt][0], af[mt][1], af[mt][2], af[mt][3],
                                 bf[j][0], bf[j][1]);
            }
        }

        // ---- add bias into acc ----
        {
            int nb = nt * 64 + ncol;
            float bv[4][2];
            #pragma unroll
            for (int j = 0; j < 4; ++j) {
                bv[j][0] = b2s[nb + j * 8 + 2 * t];
                bv[j][1] = b2s[nb + j * 8 + 2 * t + 1];
            }
            #pragma unroll
            for (int mt = 0; mt < 2; ++mt)
                #pragma unroll
                for (int j = 0; j < 4; ++j) {
                    acc[mt][j][0] += bv[j][0];
                    acc[mt][j][1] += bv[j][1];
                    acc[mt][j][2] += bv[j][0];
                    acc[mt][j][3] += bv[j][1];
                }
        }

        // ---- in-register contraction ----
        if (nt < 20) {
            // w_ss (nt<16): coef = sxs[row][2nt + ncol/32]
            // w_vs (16..19): coef = dvv[row][2(nt-16) + ncol/32]
            float cf[2][2];
            if (nt < 16) {
                int i = 2 * nt + (ncol >> 5);
                #pragma unroll
                for (int mt = 0; mt < 2; ++mt)
                    #pragma unroll
                    for (int rh = 0; rh < 2; ++rh)
                        cf[mt][rh] = sxs[rows_[mt][rh] * 32 + i];
            } else {
                int iv = 2 * (nt - 16) + (ncol >> 5);
                #pragma unroll
                for (int mt = 0; mt < 2; ++mt)
                    #pragma unroll
                    for (int rh = 0; rh < 2; ++rh)
                        cf[mt][rh] = dvv[rows_[mt][rh] * 8 + iv];
            }
            #pragma unroll
            for (int mt = 0; mt < 2; ++mt)
                #pragma unroll
                for (int j = 0; j < 4; ++j) {
                    sp[mt][j][0] += acc[mt][j][0] * cf[mt][0];
                    sp[mt][j][1] += acc[mt][j][1] * cf[mt][0];
                    sp[mt][j][2] += acc[mt][j][2] * cf[mt][1];
                    sp[mt][j][3] += acc[mt][j][3] * cf[mt][1];
                }
        } else if (nt < 24) {
            // w_sv: a2[mt][rh][re] += sum_j acc[mt][j][rh*2+re] * xs[row][ib + j]
            int ib = 8 * (nt - 20) + (ncol >> 3);
            #pragma unroll
            for (int mt = 0; mt < 2; ++mt)
                #pragma unroll
                for (int rh = 0; rh < 2; ++rh) {
                    const float* xr = &xsh[rows_[mt][rh] * 32 + ib];
                    float x0 = xr[0], x1 = xr[1], x2 = xr[2], x3 = xr[3];
                    a2[mt][rh][0] += acc[mt][0][rh * 2] * x0 + acc[mt][1][rh * 2] * x1
                                   + acc[mt][2][rh * 2] * x2 + acc[mt][3][rh * 2] * x3;
                    a2[mt][rh][1] += acc[mt][0][rh * 2 + 1] * x0 + acc[mt][1][rh * 2 + 1] * x1
                                   + acc[mt][2][rh * 2 + 1] * x2 + acc[mt][3][rh * 2 + 1] * x3;
                }
        } else {
            // nt == 24: w_vv + finalize vector outputs
            int ixb = (ncol >> 3);
            #pragma unroll
            for (int mt = 0; mt < 2; ++mt)
                #pragma unroll
                for (int rh = 0; rh < 2; ++rh) {
                    int row = rows_[mt][rh];
                    int src = esrc[row];
                    const float* xv = &xvs[row * 24 + ixb * 3];
                    const float* sv = &svs[row * 3];
                    #pragma unroll
                    for (int re = 0; re < 2; ++re) {
                        int q = rh * 2 + re;
                        int ch = 32 + (2 * t + re) * 3;
                        float a2v = a2[mt][rh][re];
                        #pragma unroll
                        for (int m = 0; m < 3; ++m) {
                            float vv = acc[mt][0][q] * xv[0 * 3 + m]
                                     + acc[mt][1][q] * xv[1 * 3 + m]
                                     + acc[mt][2][q] * xv[2 * 3 + m]
                                     + acc[mt][3][q] * xv[3 * 3 + m];
                            atomicAdd(&g_sums[(size_t)src * DD + ch + m],
                                      (a2v * sv[m] + vv) * PATH_NORM);
                        }
                    }
                }
        }
    }

    // ---- scalar scatter ----
    #pragma unroll
    for (int mt = 0; mt < 2; ++mt)
        #pragma unroll
        for (int rh = 0; rh < 2; ++rh) {
            int row = rows_[mt][rh];
            int src = esrc[row];
            #pragma unroll
            for (int j = 0; j < 4; ++j) {
                int ch = j * 8 + 2 * t;
                atomicAdd(&g_sums[(size_t)src * DD + ch],     sp[mt][j][rh * 2] * PATH_NORM);
                atomicAdd(&g_sums[(size_t)src * DD + ch + 1], sp[mt][j][rh * 2 + 1] * PATH_NORM);
            }
        }
    if (tid < 128) atomicAdd(&g_cnt[esrc[tid]], 1.0f);
}

// ============================================================
// K4: pre = sums/max(cnt,1) + node_attr ; BN stats
// ============================================================
__global__ void k4_pre_stats(const float* __restrict__ node_attr) {
    __shared__ float bins[72];
    int tid = threadIdx.x;
    if (tid < 72) bins[tid] = 0.f;
    __syncthreads();
    int idx = blockIdx.x * 256 + tid;
    int n = idx / DD, f = idx - n * DD;
    float val = g_sums[idx] / fmaxf(g_cnt[n], 1.0f) + node_attr[idx];
    g_pre[idx] = val;
    if (f < NS) {
        atomicAdd(&bins[f], val);
        atomicAdd(&bins[32 + f], val * val);
    } else {
        atomicAdd(&bins[64 + (f - NS) / 3], val * val);
    }
    __syncthreads();
    if (tid < 72) atomicAdd(&g_stats[tid], bins[tid]);
}

// ============================================================
// K5: batch-norm finalize -> out
// ============================================================
__global__ void k5_norm(const float* __restrict__ gamma,
                        const float* __restrict__ beta,
                        float* __restrict__ out) {
    int idx = blockIdx.x * 256 + threadIdx.x;
    int f = idx % DD;
    float val = g_pre[idx];
    float o;
    if (f < NS) {
        float mean = g_stats[f] * (1.0f / N_NODES);
        float var  = g_stats[32 + f] * (1.0f / N_NODES) - mean * mean;
        o = (val - mean) * rsqrtf(var + EPS) * gamma[f] + beta[f];
    } else {
        int i = (f - NS) / 3;
        float vn2 = g_stats[64 + i] * (1.0f / N_NODES);
        o = val * rsqrtf(vn2 + EPS) * gamma[NS + i];
    }
    out[idx] = o;
}

// ============================================================
extern "C" void kernel_launch(void* const* d_in, const int* in_sizes, int n_in,
                              void* d_out, int out_size) {
    const float* node_attr = nullptr;
    const float* edge_attr = nullptr;
    const float* edge_sh   = nullptr;
    const float* W1 = nullptr;
    const float* b1 = nullptr;
    const float* W2 = nullptr;
    const float* b2 = nullptr;
    const float* gamma = nullptr;
    const float* beta  = nullptr;
    const long long* eidx = nullptr;

    for (int i = 0; i < n_in; ++i) {
        switch (in_sizes[i]) {
            case 917504:   node_attr = (const float*)d_in[i]; break;
            case 16777216: edge_attr = (const float*)d_in[i]; break;
            case 524288:   edge_sh   = (const float*)d_in[i]; break;
            case 16384:    W1 = (const float*)d_in[i]; break;
            case 128:      b1 = (const float*)d_in[i]; break;
            case 204800:   W2 = (const float*)d_in[i]; break;
            case 1600:     b2 = (const float*)d_in[i]; break;
            case 40:       gamma = (const float*)d_in[i]; break;
            case 32:       beta  = (const float*)d_in[i]; break;
            case 262144:   eidx = (const long long*)d_in[i]; break;
            default: break;
        }
    }
    float* out = (float*)d_out;
    (void)out_size;

    cudaFuncSetAttribute(k1_gemm_relu, cudaFuncAttributeMaxDynamicSharedMemorySize, 131072);
    cudaFuncSetAttribute(k2_fused,     cudaFuncAttributeMaxDynamicSharedMemorySize, K2_SMEM);

    k0_zero<<<3584, 256>>>(eidx);
    k_prep<<<(1664 * HID + 255) / 256, 256>>>(W2);
    k1_gemm_relu<<<N_EDGES / 128, 256, 131072>>>(edge_attr, W1, b1);
    k2_fused<<<N_EDGES / 128, 256, K2_SMEM>>>(node_attr, edge_sh, b2, eidx);
    k4_pre_stats<<<(N_NODES * DD) / 256, 256>>>(node_attr);
    k5_norm<<<(N_NODES * DD) / 256, 256>>>(gamma, beta, out);
}